// round 1
// baseline (speedup 1.0000x reference)
#include <cuda_runtime.h>

#define N_  2
#define C_  128
#define D_  32
#define H_  64
#define W_  64
#define R_  256
#define PD  4
#define PH  7
#define PW  7
#define DHW (D_ * H_ * W_)

// 128 MB static scratch for NDHWC-transposed features (allowed: static __device__, no dynamic alloc)
__device__ float g_feat_t[(size_t)N_ * DHW * C_];

// ---------------------------------------------------------------------------
// Transpose NCDHW -> NDHWC  (per n: 2D transpose of [C=128, DHW=131072])
// ---------------------------------------------------------------------------
__global__ void __launch_bounds__(256) transpose_ndhwc(const float* __restrict__ in,
                                                       float* __restrict__ out) {
    __shared__ float tile[32][33];
    const int n  = blockIdx.z;
    const int s0 = blockIdx.x * 32;   // spatial (dhw) tile origin
    const int c0 = blockIdx.y * 32;   // channel tile origin
    const int tx = threadIdx.x, ty = threadIdx.y;

    const float* ip = in  + (size_t)n * C_ * DHW;
    float*       op = out + (size_t)n * DHW * C_;

#pragma unroll
    for (int i = 0; i < 32; i += 8)
        tile[ty + i][tx] = ip[(size_t)(c0 + ty + i) * DHW + (s0 + tx)];
    __syncthreads();
#pragma unroll
    for (int i = 0; i < 32; i += 8)
        op[(size_t)(s0 + ty + i) * C_ + (c0 + tx)] = tile[tx][ty + i];
}

// ---------------------------------------------------------------------------
// RoIAlign 3D main kernel
//   grid:  (R, PH*PW)      block: (32, PD)
//   threadIdx.x = float4 channel group (32 * 4 = 128 channels)
//   threadIdx.y = pd
// ---------------------------------------------------------------------------
__device__ __forceinline__ void axis1(float c, int size, int& lo, int& hi,
                                      float& w, bool& v) {
    v = (c >= -1.0f) && (c <= (float)size);
    c = fminf(fmaxf(c, 0.0f), (float)size - 1.0f);
    float lf = floorf(c);
    lo = (int)lf;
    hi = min(lo + 1, size - 1);
    w = c - lf;
}

__global__ void __launch_bounds__(32 * PD) roi3d_kernel(const float* __restrict__ rois,
                                                        const float* __restrict__ feat,
                                                        float* __restrict__ out) {
    const int r    = blockIdx.x;
    const int cell = blockIdx.y;           // ph*PW + pw
    const int ph   = cell / PW;
    const int pw   = cell - ph * PW;
    const int pd   = threadIdx.y;
    const int c4   = threadIdx.x;          // float4 group index

    const float* roi = rois + r * 7;
    const int   b  = (int)roi[0];
    const float x1 = roi[1] * 0.25f, y1 = roi[2] * 0.25f, z1 = roi[3] * 0.25f;
    const float x2 = roi[4] * 0.25f, y2 = roi[5] * 0.25f, z2 = roi[6] * 0.25f;
    const float rd = fmaxf(z2 - z1, 1.0f);
    const float rh = fmaxf(y2 - y1, 1.0f);
    const float rw = fmaxf(x2 - x1, 1.0f);
    const float sz = rd * (1.0f / (PD * 2));
    const float sy = rh * (1.0f / (PH * 2));
    const float sx = rw * (1.0f / (PW * 2));

    const float4* fp    = (const float4*)feat;
    const size_t  bbase = (size_t)b * DHW;   // voxel base for this batch

    float4 acc = make_float4(0.0f, 0.0f, 0.0f, 0.0f);

#pragma unroll
    for (int iz = 0; iz < 2; iz++) {
        float zc; int zlo, zhi; float wz; bool vz;
        zc = z1 + ((float)(pd * 2 + iz) + 0.5f) * sz;
        axis1(zc, D_, zlo, zhi, wz, vz);
        const size_t vzl = bbase + (size_t)zlo * (H_ * W_);
        const size_t vzh = bbase + (size_t)zhi * (H_ * W_);
#pragma unroll
        for (int iy = 0; iy < 2; iy++) {
            float yc; int ylo, yhi; float wy; bool vy;
            yc = y1 + ((float)(ph * 2 + iy) + 0.5f) * sy;
            axis1(yc, H_, ylo, yhi, wy, vy);
            const int oyl = ylo * W_;
            const int oyh = yhi * W_;
#pragma unroll
            for (int ix = 0; ix < 2; ix++) {
                float xc; int xlo, xhi; float wx; bool vx;
                xc = x1 + ((float)(pw * 2 + ix) + 0.5f) * sx;
                axis1(xc, W_, xlo, xhi, wx, vx);
                if (!(vz && vy && vx)) continue;

                const float wz0 = 1.0f - wz, wy0 = 1.0f - wy, wx0 = 1.0f - wx;
                const float w000 = wz0 * wy0 * wx0;
                const float w001 = wz0 * wy0 * wx;
                const float w010 = wz0 * wy  * wx0;
                const float w011 = wz0 * wy  * wx;
                const float w100 = wz  * wy0 * wx0;
                const float w101 = wz  * wy0 * wx;
                const float w110 = wz  * wy  * wx0;
                const float w111 = wz  * wy  * wx;

                // float4 element index = voxel * (C_/4) + c4
                const float4 f000 = fp[(vzl + oyl + xlo) * (C_ / 4) + c4];
                const float4 f001 = fp[(vzl + oyl + xhi) * (C_ / 4) + c4];
                const float4 f010 = fp[(vzl + oyh + xlo) * (C_ / 4) + c4];
                const float4 f011 = fp[(vzl + oyh + xhi) * (C_ / 4) + c4];
                const float4 f100 = fp[(vzh + oyl + xlo) * (C_ / 4) + c4];
                const float4 f101 = fp[(vzh + oyl + xhi) * (C_ / 4) + c4];
                const float4 f110 = fp[(vzh + oyh + xlo) * (C_ / 4) + c4];
                const float4 f111 = fp[(vzh + oyh + xhi) * (C_ / 4) + c4];

                acc.x += f000.x * w000 + f001.x * w001 + f010.x * w010 + f011.x * w011
                       + f100.x * w100 + f101.x * w101 + f110.x * w110 + f111.x * w111;
                acc.y += f000.y * w000 + f001.y * w001 + f010.y * w010 + f011.y * w011
                       + f100.y * w100 + f101.y * w101 + f110.y * w110 + f111.y * w111;
                acc.z += f000.z * w000 + f001.z * w001 + f010.z * w010 + f011.z * w011
                       + f100.z * w100 + f101.z * w101 + f110.z * w110 + f111.z * w111;
                acc.w += f000.w * w000 + f001.w * w001 + f010.w * w010 + f011.w * w011
                       + f100.w * w100 + f101.w * w101 + f110.w * w110 + f111.w * w111;
            }
        }
    }

    const float inv = 0.125f;  // mean over sr^3 = 8 samples
    const int   c   = c4 * 4;
    // out[r][c][pd][ph][pw]
    size_t ob = (((size_t)r * C_ + c) * PD + pd) * (PH * PW) + cell;
    out[ob]                      = acc.x * inv;
    out[ob + 1 * PD * PH * PW]   = acc.y * inv;
    out[ob + 2 * PD * PH * PW]   = acc.z * inv;
    out[ob + 3 * PD * PH * PW]   = acc.w * inv;
}

// ---------------------------------------------------------------------------
extern "C" void kernel_launch(void* const* d_in, const int* in_sizes, int n_in,
                              void* d_out, int out_size) {
    const float* features = (const float*)d_in[0];
    const float* rois     = (const float*)d_in[1];
    float*       out      = (float*)d_out;

    float* feat_t = nullptr;
    cudaGetSymbolAddress((void**)&feat_t, g_feat_t);

    // 1) NCDHW -> NDHWC
    dim3 tg(DHW / 32, C_ / 32, N_);
    dim3 tb(32, 8);
    transpose_ndhwc<<<tg, tb>>>(features, feat_t);

    // 2) RoIAlign gather
    dim3 rg(R_, PH * PW);
    dim3 rb(32, PD);
    roi3d_kernel<<<rg, rb>>>(rois, feat_t, out);
}

// round 3
// speedup vs baseline: 1.0896x; 1.0896x over previous
#include <cuda_runtime.h>

#define N_  2
#define C_  128
#define D_  32
#define H_  64
#define W_  64
#define R_  256
#define PD  4
#define PH  7
#define PW  7
#define HW_ (H_ * W_)
#define DHW (D_ * H_ * W_)

// 128 MB static scratch for NDHWC-transposed features
__device__ float g_feat_t[(size_t)N_ * DHW * C_];

// ---------------------------------------------------------------------------
// Transpose NCDHW -> NDHWC  (per n: 2D transpose of [C=128, DHW=131072])
// ---------------------------------------------------------------------------
__global__ void __launch_bounds__(256) transpose_ndhwc(const float* __restrict__ in,
                                                       float* __restrict__ out) {
    __shared__ float tile[32][33];
    const int n  = blockIdx.z;
    const int s0 = blockIdx.x * 32;   // spatial (dhw) tile origin
    const int c0 = blockIdx.y * 32;   // channel tile origin
    const int tx = threadIdx.x, ty = threadIdx.y;

    const float* ip = in  + (size_t)n * C_ * DHW;
    float*       op = out + (size_t)n * DHW * C_;

#pragma unroll
    for (int i = 0; i < 32; i += 8)
        tile[ty + i][tx] = ip[(size_t)(c0 + ty + i) * DHW + (s0 + tx)];
    __syncthreads();
#pragma unroll
    for (int i = 0; i < 32; i += 8)
        op[(size_t)(s0 + ty + i) * C_ + (c0 + tx)] = tile[tx][ty + i];
}

// ---------------------------------------------------------------------------
// Per-axis separable tap accumulation.
// Two samples (c0 < c1) per cell per axis; their 4 bilinear taps land on
// <= 4 distinct integer coords in window [floor(clamp(c0)), +3].
// Returns base coord and 4 summed weights (0 => no load needed).
// ---------------------------------------------------------------------------
__device__ __forceinline__ void axis_taps(float c0, float c1, int size,
                                          int& base, float w[4]) {
    w[0] = w[1] = w[2] = w[3] = 0.0f;
    const float szf = (float)size;

    const bool v0 = (c0 >= -1.0f) && (c0 <= szf);
    float cc0 = fminf(fmaxf(c0, 0.0f), szf - 1.0f);
    const int lo0 = (int)floorf(cc0);
    const int hi0 = min(lo0 + 1, size - 1);
    const float f0 = cc0 - (float)lo0;

    const bool v1 = (c1 >= -1.0f) && (c1 <= szf);
    float cc1 = fminf(fmaxf(c1, 0.0f), szf - 1.0f);
    const int lo1 = (int)floorf(cc1);
    const int hi1 = min(lo1 + 1, size - 1);
    const float f1 = cc1 - (float)lo1;

    base = lo0;                      // lo0 <= lo1 (clamp is monotone)
    if (v0) { w[0]        += 1.0f - f0; w[hi0 - lo0] += f0; }
    if (v1) { w[lo1 - lo0] += 1.0f - f1; w[hi1 - lo0] += f1; }
}

// ---------------------------------------------------------------------------
// RoIAlign 3D gather (separable-weight form)
//   grid:  (R, PH*PW)   block: (32, PD)
//   threadIdx.x = float4 channel group, threadIdx.y = pd
//   All weights/indices are uniform across a warp (lanes differ only in c4),
//   so the zero-weight skips are non-divergent.
// ---------------------------------------------------------------------------
__global__ void __launch_bounds__(32 * PD) roi3d_kernel(const float* __restrict__ rois,
                                                        const float* __restrict__ feat,
                                                        float* __restrict__ out) {
    const int r    = blockIdx.x;
    const int cell = blockIdx.y;           // ph*PW + pw
    const int ph   = cell / PW;
    const int pw   = cell - ph * PW;
    const int pd   = threadIdx.y;
    const int c4   = threadIdx.x;

    const float* roi = rois + r * 7;
    const int   b  = (int)roi[0];
    const float x1 = roi[1] * 0.25f, y1 = roi[2] * 0.25f, z1 = roi[3] * 0.25f;
    const float x2 = roi[4] * 0.25f, y2 = roi[5] * 0.25f, z2 = roi[6] * 0.25f;
    const float rd = fmaxf(z2 - z1, 1.0f);
    const float rh = fmaxf(y2 - y1, 1.0f);
    const float rw = fmaxf(x2 - x1, 1.0f);
    const float sz = rd * (1.0f / (PD * 2));
    const float sy = rh * (1.0f / (PH * 2));
    const float sx = rw * (1.0f / (PW * 2));

    // two sample coordinates per axis for this cell
    const float zc0 = z1 + ((float)(pd * 2) + 0.5f) * sz;
    const float yc0 = y1 + ((float)(ph * 2) + 0.5f) * sy;
    const float xc0 = x1 + ((float)(pw * 2) + 0.5f) * sx;

    int bz, by, bx;
    float wz[4], wy[4], wx[4];
    axis_taps(zc0, zc0 + sz, D_, bz, wz);
    axis_taps(yc0, yc0 + sy, H_, by, wy);
    axis_taps(xc0, xc0 + sx, W_, bx, wx);

    const float4* __restrict__ fp = (const float4*)feat;
    const int bbase = b * DHW;             // fits in int (float4 units: 8.4M max)

    float4 acc = make_float4(0.0f, 0.0f, 0.0f, 0.0f);

#pragma unroll
    for (int zi = 0; zi < 4; zi++) {
        const float wzv = wz[zi];
        if (wzv == 0.0f) continue;
        const int zoff = bbase + (bz + zi) * HW_;
#pragma unroll
        for (int yi = 0; yi < 4; yi++) {
            const float wzy = wzv * wy[yi];
            if (wzy == 0.0f) continue;
            const int yoff = (zoff + (by + yi) * W_ + bx) * (C_ / 4) + c4;
#pragma unroll
            for (int xi = 0; xi < 4; xi++) {
                const float w = wzy * wx[xi];
                if (w == 0.0f) continue;
                const float4 f = fp[yoff + xi * (C_ / 4)];
                acc.x += f.x * w;
                acc.y += f.y * w;
                acc.z += f.z * w;
                acc.w += f.w * w;
            }
        }
    }

    const float inv = 0.125f;  // mean over sr^3 = 8 samples
    const int   c   = c4 * 4;
    // out[r][c][pd][ph][pw]
    int ob = (((r * C_ + c) * PD + pd) * (PH * PW)) + cell;
    out[ob]                    = acc.x * inv;
    out[ob + 1 * PD * PH * PW] = acc.y * inv;
    out[ob + 2 * PD * PH * PW] = acc.z * inv;
    out[ob + 3 * PD * PH * PW] = acc.w * inv;
}

// ---------------------------------------------------------------------------
extern "C" void kernel_launch(void* const* d_in, const int* in_sizes, int n_in,
                              void* d_out, int out_size) {
    const float* features = (const float*)d_in[0];
    const float* rois     = (const float*)d_in[1];
    float*       out      = (float*)d_out;

    float* feat_t = nullptr;
    cudaGetSymbolAddress((void**)&feat_t, g_feat_t);

    // 1) NCDHW -> NDHWC
    dim3 tg(DHW / 32, C_ / 32, N_);
    dim3 tb(32, 8);
    transpose_ndhwc<<<tg, tb>>>(features, feat_t);

    // 2) RoIAlign gather (separable weights)
    dim3 rg(R_, PH * PW);
    dim3 rb(32, PD);
    roi3d_kernel<<<rg, rb>>>(rois, feat_t, out);
}